// round 6
// baseline (speedup 1.0000x reference)
#include <cuda_runtime.h>
#include <cuda_bf16.h>
#include <math.h>

// ---------------------------------------------------------------------------
// UniCL loss, N=8192, D=512.
//   S = 2.659 * normalize(img) @ normalize(txt)^T
//   loss = ( softCE(S, T) + softCE(S^T, T) ) / 2,  T symmetric 0/1 target.
// Since |S| <= 2.659, logsumexp needs no max subtraction:
//   row_loss_i = log(sum_j exp(S_ij)) - (sum_j T_ij S_ij)/cnt_i
//   col_loss_j = log(sum_i exp(S_ij)) - (sum_i T_ij S_ij)/cnt_j
// cnt_i = hist[label_i] (or 1 if label == -1).
// NOTE: labels arrive as int32 (JAX x64-disabled truncates int64 -> int32).
// ---------------------------------------------------------------------------

#define NROWS 8192
#define DDIM  512
#define LOGIT_SCALE 2.659f

#define BM 128
#define BN 128
#define BK 16
#define TM 8
#define TN 8
#define NBLK (NROWS / BN)   // 64 column/row blocks

// -------- device scratch (static: no allocation in kernel_launch) ----------
__device__ float g_txtn[NROWS * DDIM];   // normalized text features
__device__ float g_imgn[NROWS * DDIM];   // normalized image features
__device__ float g_partZr[NBLK * NROWS]; // [colBlock][row]  sum exp
__device__ float g_partTr[NBLK * NROWS]; // [colBlock][row]  sum t*s
__device__ float g_partZc[NBLK * NROWS]; // [rowBlock][col]  sum exp
__device__ float g_partTc[NBLK * NROWS]; // [rowBlock][col]  sum t*s
__device__ int   g_hist[128];
__device__ float g_loss[NROWS];

// ---------------------------------------------------------------------------
// 1) row L2 normalize: grid (NROWS, 2), 128 threads (each thread = 1 float4)
// ---------------------------------------------------------------------------
__global__ void normalize_kernel(const float* __restrict__ txt,
                                 const float* __restrict__ img) {
    const float* src = (blockIdx.y == 0) ? txt : img;
    float*       dst = (blockIdx.y == 0) ? g_txtn : g_imgn;
    const int row = blockIdx.x;
    const int tid = threadIdx.x;

    float4 v = *(const float4*)(src + (size_t)row * DDIM + tid * 4);
    float ss = v.x * v.x + v.y * v.y + v.z * v.z + v.w * v.w;

    #pragma unroll
    for (int o = 16; o >= 1; o >>= 1) ss += __shfl_xor_sync(0xffffffffu, ss, o);

    __shared__ float sh[4];
    if ((tid & 31) == 0) sh[tid >> 5] = ss;
    __syncthreads();
    ss = sh[0] + sh[1] + sh[2] + sh[3];

    float inv = 1.0f / fmaxf(sqrtf(ss), 1e-12f);
    v.x *= inv; v.y *= inv; v.z *= inv; v.w *= inv;
    *(float4*)(dst + (size_t)row * DDIM + tid * 4) = v;
}

// ---------------------------------------------------------------------------
// 2) label histogram (zero + build; int atomics => deterministic)
// ---------------------------------------------------------------------------
__global__ void zero_hist_kernel() {
    if (threadIdx.x < 128) g_hist[threadIdx.x] = 0;
}

__global__ void hist_kernel(const int* __restrict__ labels) {
    int i = blockIdx.x * blockDim.x + threadIdx.x;
    if (i < NROWS) {
        int l = labels[i];
        if (l >= 0 && l < 128) atomicAdd(&g_hist[l], 1);
    }
}

// ---------------------------------------------------------------------------
// 3) fused GEMM + exp/target stats. Grid (64, 64), 256 threads.
//    Each CTA: 128x128 tile of S over K=512, then row/col partial sums.
// ---------------------------------------------------------------------------
__global__ __launch_bounds__(256, 2)
void gemm_stats_kernel(const int* __restrict__ labels) {
    __shared__ float As[BK][BM];
    __shared__ float Bs[BK][BN];
    __shared__ int   rlab[BM];
    __shared__ int   clab[BN];

    const int bn = blockIdx.x;          // column block
    const int bm = blockIdx.y;          // row block
    const int row0 = bm * BM;
    const int col0 = bn * BN;
    const int tid = threadIdx.x;
    const int tx = tid & 15;            // 0..15  -> cols tx*8..
    const int ty = tid >> 4;            // 0..15  -> rows ty*8..

    if (tid < BM) rlab[tid] = labels[row0 + tid];
    else          clab[tid - BM] = labels[col0 + (tid - BM)];

    const float* __restrict__ A = g_imgn;   // rows of S  = image
    const float* __restrict__ B = g_txtn;   // cols of S  = text

    float acc[TM][TN];
    #pragma unroll
    for (int m = 0; m < TM; m++)
        #pragma unroll
        for (int n = 0; n < TN; n++) acc[m][n] = 0.0f;

    const int lr = tid >> 2;          // 0..63
    const int lk = (tid & 3) * 4;     // 0,4,8,12

    for (int k0 = 0; k0 < DDIM; k0 += BK) {
        float4 a0 = *(const float4*)(A + (size_t)(row0 + lr)      * DDIM + k0 + lk);
        float4 a1 = *(const float4*)(A + (size_t)(row0 + lr + 64) * DDIM + k0 + lk);
        float4 b0 = *(const float4*)(B + (size_t)(col0 + lr)      * DDIM + k0 + lk);
        float4 b1 = *(const float4*)(B + (size_t)(col0 + lr + 64) * DDIM + k0 + lk);

        __syncthreads();
        As[lk + 0][lr] = a0.x; As[lk + 1][lr] = a0.y;
        As[lk + 2][lr] = a0.z; As[lk + 3][lr] = a0.w;
        As[lk + 0][lr + 64] = a1.x; As[lk + 1][lr + 64] = a1.y;
        As[lk + 2][lr + 64] = a1.z; As[lk + 3][lr + 64] = a1.w;
        Bs[lk + 0][lr] = b0.x; Bs[lk + 1][lr] = b0.y;
        Bs[lk + 2][lr] = b0.z; Bs[lk + 3][lr] = b0.w;
        Bs[lk + 0][lr + 64] = b1.x; Bs[lk + 1][lr + 64] = b1.y;
        Bs[lk + 2][lr + 64] = b1.z; Bs[lk + 3][lr + 64] = b1.w;
        __syncthreads();

        #pragma unroll
        for (int k = 0; k < BK; k++) {
            float a[TM], b[TN];
            *(float4*)(a)     = *(const float4*)(&As[k][ty * TM]);
            *(float4*)(a + 4) = *(const float4*)(&As[k][ty * TM + 4]);
            *(float4*)(b)     = *(const float4*)(&Bs[k][tx * TN]);
            *(float4*)(b + 4) = *(const float4*)(&Bs[k][tx * TN + 4]);
            #pragma unroll
            for (int m = 0; m < TM; m++)
                #pragma unroll
                for (int n = 0; n < TN; n++)
                    acc[m][n] = fmaf(a[m], b[n], acc[m][n]);
        }
    }

    // ---- epilogue: per-tile stats --------------------------------------
    float zrow[TM], trow[TM], zcol[TN], tcol[TN];
    #pragma unroll
    for (int m = 0; m < TM; m++) { zrow[m] = 0.0f; trow[m] = 0.0f; }
    #pragma unroll
    for (int n = 0; n < TN; n++) { zcol[n] = 0.0f; tcol[n] = 0.0f; }

    int cl[TN], gj[TN];
    #pragma unroll
    for (int n = 0; n < TN; n++) {
        cl[n] = clab[tx * TN + n];
        gj[n] = col0 + tx * TN + n;
    }

    #pragma unroll
    for (int m = 0; m < TM; m++) {
        const int gi = row0 + ty * TM + m;
        const int rl = rlab[ty * TM + m];
        #pragma unroll
        for (int n = 0; n < TN; n++) {
            float s = acc[m][n] * LOGIT_SCALE;
            float e = __expf(s);
            zrow[m] += e;
            zcol[n] += e;
            bool tmatch = (gi == gj[n]) || (rl >= 0 && rl == cl[n]);
            if (tmatch) { trow[m] += s; tcol[n] += s; }
        }
    }

    // row reduce across the 16 threads sharing a row group (16-lane segments)
    #pragma unroll
    for (int m = 0; m < TM; m++) {
        #pragma unroll
        for (int o = 8; o >= 1; o >>= 1) {
            zrow[m] += __shfl_xor_sync(0xffffffffu, zrow[m], o, 16);
            trow[m] += __shfl_xor_sync(0xffffffffu, trow[m], o, 16);
        }
    }
    if (tx == 0) {
        #pragma unroll
        for (int m = 0; m < TM; m++) {
            int gi = row0 + ty * TM + m;
            g_partZr[(size_t)bn * NROWS + gi] = zrow[m];
            g_partTr[(size_t)bn * NROWS + gi] = trow[m];
        }
    }

    // column reduce via smem (reuse As/Bs: exactly 16 x 128 each)
    __syncthreads();
    #pragma unroll
    for (int n = 0; n < TN; n++) {
        As[ty][tx * TN + n] = zcol[n];
        Bs[ty][tx * TN + n] = tcol[n];
    }
    __syncthreads();
    if (tid < BN) {
        float z = 0.0f, t = 0.0f;
        #pragma unroll
        for (int r = 0; r < 16; r++) { z += As[r][tid]; t += Bs[r][tid]; }
        g_partZc[(size_t)bm * NROWS + col0 + tid] = z;
        g_partTc[(size_t)bm * NROWS + col0 + tid] = t;
    }
}

// ---------------------------------------------------------------------------
// 4) per-row final: combine 64 partials, form per-index loss contribution
// ---------------------------------------------------------------------------
__global__ void reduce_rows_kernel(const int* __restrict__ labels) {
    int i = blockIdx.x * blockDim.x + threadIdx.x;
    if (i >= NROWS) return;
    float zr = 0.0f, tr = 0.0f, zc = 0.0f, tc = 0.0f;
    #pragma unroll 8
    for (int b = 0; b < NBLK; b++) {
        zr += g_partZr[(size_t)b * NROWS + i];
        tr += g_partTr[(size_t)b * NROWS + i];
        zc += g_partZc[(size_t)b * NROWS + i];
        tc += g_partTc[(size_t)b * NROWS + i];
    }
    int l = labels[i];
    float cnt = (l < 0) ? 1.0f : (float)g_hist[l];
    g_loss[i] = (logf(zr) - tr / cnt) + (logf(zc) - tc / cnt);
}

// ---------------------------------------------------------------------------
// 5) scalar reduction: out = sum(g_loss) / (2N)  == (mean_img + mean_txt)/2
// ---------------------------------------------------------------------------
__global__ void final_sum_kernel(float* __restrict__ out) {
    __shared__ float sh[256];
    float s = 0.0f;
    for (int i = threadIdx.x; i < NROWS; i += 256) s += g_loss[i];
    sh[threadIdx.x] = s;
    __syncthreads();
    for (int o = 128; o > 0; o >>= 1) {
        if (threadIdx.x < o) sh[threadIdx.x] += sh[threadIdx.x + o];
        __syncthreads();
    }
    if (threadIdx.x == 0) out[0] = sh[0] / (2.0f * (float)NROWS);
}

// ---------------------------------------------------------------------------
extern "C" void kernel_launch(void* const* d_in, const int* in_sizes, int n_in,
                              void* d_out, int out_size) {
    const float* txt    = (const float*)d_in[0];   // text_features
    const float* img    = (const float*)d_in[1];   // image_features
    const int*   labels = (const int*)d_in[2];     // labels (int32)
    float* out = (float*)d_out;

    normalize_kernel<<<dim3(NROWS, 2), 128>>>(txt, img);
    zero_hist_kernel<<<1, 128>>>();
    hist_kernel<<<NROWS / 256, 256>>>(labels);
    gemm_stats_kernel<<<dim3(NBLK, NBLK), 256>>>(labels);
    reduce_rows_kernel<<<NROWS / 256, 256>>>(labels);
    final_sum_kernel<<<1, 256>>>(out);
}

// round 8
// speedup vs baseline: 3.4347x; 3.4347x over previous
#include <cuda_runtime.h>
#include <cuda_bf16.h>
#include <math.h>
#include <stdint.h>

// ===========================================================================
// UniCL loss, N=8192, D=512 — mma.sync bf16 hi/lo-split GEMM + fused stats.
//   S = 2.659 * normalize(img) @ normalize(txt)^T   (|S| <= 2.659)
//   row_loss_i = log(sum_j exp(S_ij)) - (sum_j T_ij S_ij)/cnt_i   (cols same)
// Split: x = hi + lo (bf16 each), concat along K -> K=1024 bf16 GEMM == fp32.
// (tcgen05 is unavailable: harness builds base compute_103 PTX.)
// ===========================================================================

#define NROWS 8192
#define DDIM  512
#define KTOT  1024
#define LOGIT_SCALE 2.659f

#define BM 128
#define BN 128
#define NITER 16            // K chunks of 64 bf16 (128 B)
#define NSTAGE 3
#define STAGE_BYTES 32768u  // A 16 KB + B 16 KB
#define DYNSMEM (NSTAGE * STAGE_BYTES)
#define NBLK 64             // 8192 / 128

// ---- device scratch --------------------------------------------------------
__device__ __nv_bfloat16 g_txt_bf[NROWS * KTOT];
__device__ __nv_bfloat16 g_img_bf[NROWS * KTOT];
__device__ float g_partZr[NBLK * NROWS];
__device__ float g_partTr[NBLK * NROWS];
__device__ float g_partZc[NBLK * NROWS];
__device__ float g_partTc[NBLK * NROWS];
__device__ int   g_hist[128];
__device__ float g_loss[NROWS];

__device__ __forceinline__ uint32_t smem_u32(const void* p) {
    uint32_t a;
    asm("{ .reg .u64 t; cvta.to.shared.u64 t, %1; cvt.u32.u64 %0, t; }"
        : "=r"(a) : "l"(p));
    return a;
}
#define SWZ(b) ((b) ^ (((b) >> 3) & 0x70))

#define LDSM4(r, a)                                                            \
    asm volatile("ldmatrix.sync.aligned.m8n8.x4.shared.b16 {%0,%1,%2,%3}, [%4];" \
                 : "=r"((r)[0]), "=r"((r)[1]), "=r"((r)[2]), "=r"((r)[3])      \
                 : "r"(a))

static __device__ __forceinline__ void mma16816(float* d, const uint32_t* a,
                                                const uint32_t* b) {
    asm volatile(
        "mma.sync.aligned.m16n8k16.row.col.f32.bf16.bf16.f32 "
        "{%0,%1,%2,%3}, {%4,%5,%6,%7}, {%8,%9}, {%0,%1,%2,%3};"
        : "+f"(d[0]), "+f"(d[1]), "+f"(d[2]), "+f"(d[3])
        : "r"(a[0]), "r"(a[1]), "r"(a[2]), "r"(a[3]), "r"(b[0]), "r"(b[1]));
}

// ---------------------------------------------------------------------------
// 1) normalize + bf16 hi/lo split. grid (8192, 2), 128 threads.
// ---------------------------------------------------------------------------
__global__ void normalize_split_kernel(const float* __restrict__ txt,
                                       const float* __restrict__ img) {
    const float* src = blockIdx.y ? img : txt;
    __nv_bfloat16* dst = blockIdx.y ? g_img_bf : g_txt_bf;
    const int row = blockIdx.x, tid = threadIdx.x;

    float4 v = *(const float4*)(src + (size_t)row * DDIM + tid * 4);
    float ss = v.x * v.x + v.y * v.y + v.z * v.z + v.w * v.w;
    #pragma unroll
    for (int o = 16; o >= 1; o >>= 1) ss += __shfl_xor_sync(0xffffffffu, ss, o);
    __shared__ float sh[4];
    if ((tid & 31) == 0) sh[tid >> 5] = ss;
    __syncthreads();
    ss = sh[0] + sh[1] + sh[2] + sh[3];
    float inv = 1.0f / fmaxf(sqrtf(ss), 1e-12f);

    float x[4] = { v.x * inv, v.y * inv, v.z * inv, v.w * inv };
    __nv_bfloat16 h[4], l[4];
    #pragma unroll
    for (int i = 0; i < 4; i++) {
        h[i] = __float2bfloat16(x[i]);
        l[i] = __float2bfloat16(x[i] - __bfloat162float(h[i]));
    }
    __nv_bfloat162* ph = (__nv_bfloat162*)(dst + (size_t)row * KTOT + tid * 4);
    __nv_bfloat162* pl = (__nv_bfloat162*)(dst + (size_t)row * KTOT + 512 + tid * 4);
    __nv_bfloat162 t;
    t.x = h[0]; t.y = h[1]; ph[0] = t;
    t.x = h[2]; t.y = h[3]; ph[1] = t;
    t.x = l[0]; t.y = l[1]; pl[0] = t;
    t.x = l[2]; t.y = l[3]; pl[1] = t;
}

// ---------------------------------------------------------------------------
// 2) label histogram
// ---------------------------------------------------------------------------
__global__ void zero_hist_kernel() { if (threadIdx.x < 128) g_hist[threadIdx.x] = 0; }

__global__ void hist_kernel(const int* __restrict__ labels) {
    int i = blockIdx.x * blockDim.x + threadIdx.x;
    if (i < NROWS) {
        int l = labels[i];
        if (l >= 0 && l < 128) atomicAdd(&g_hist[l], 1);
    }
}

// ---------------------------------------------------------------------------
// 3) mma.sync GEMM + fused stats. grid (64, 64), 256 threads.
//    Warp grid 2x4: warp tile 64x32. 3-stage cp.async pipeline.
// ---------------------------------------------------------------------------
__global__ __launch_bounds__(256, 1)
void gemm_mma_kernel(const int* __restrict__ labels) {
    extern __shared__ char sm[];
    const uint32_t smb = smem_u32(sm);
    __shared__ int rlab[128], clab[128];

    const int tid  = threadIdx.x;
    const int wid  = tid >> 5;
    const int lane = tid & 31;
    const int bn = blockIdx.x, bm = blockIdx.y;
    const int row0 = bm * BM, col0 = bn * BN;
    const int wm = wid >> 2;     // 0..1  (64 rows each)
    const int wn = wid & 3;      // 0..3  (32 cols each)

    if (tid < 128) rlab[tid] = labels[row0 + tid];
    else           clab[tid - 128] = labels[col0 + (tid - 128)];

    const char* Ag = (const char*)g_img_bf + (size_t)row0 * (KTOT * 2);
    const char* Bg = (const char*)g_txt_bf + (size_t)col0 * (KTOT * 2);

    // issue one 128B-deep k-chunk for A and B into stage buffer
    auto issue = [&](int st) {
        uint32_t sb = smb + (uint32_t)(st % NSTAGE) * STAGE_BYTES;
        #pragma unroll
        for (int t = 0; t < 8; t++) {
            int idx = t * 256 + tid;           // 0..2047
            int isB = idx >> 10;
            int r   = (idx >> 3) & 127;
            int c   = idx & 7;
            const char* g = (isB ? Bg : Ag) + (size_t)r * (KTOT * 2) + st * 128 + c * 16;
            uint32_t d = sb + (isB ? 16384u : 0u) + SWZ((uint32_t)(r * 128 + c * 16));
            asm volatile("cp.async.cg.shared.global [%0], [%1], 16;"
                         :: "r"(d), "l"(g) : "memory");
        }
    };

    issue(0); asm volatile("cp.async.commit_group;" ::: "memory");
    issue(1); asm volatile("cp.async.commit_group;" ::: "memory");

    float acc[4][4][4];
    #pragma unroll
    for (int mi = 0; mi < 4; mi++)
        #pragma unroll
        for (int ni = 0; ni < 4; ni++)
            #pragma unroll
            for (int e = 0; e < 4; e++) acc[mi][ni][e] = 0.0f;

    const int rr = lane & 7;
    const int q  = lane >> 3;

    #pragma unroll 1
    for (int it = 0; it < NITER; it++) {
        if (it + 2 < NITER) issue(it + 2);
        asm volatile("cp.async.commit_group;" ::: "memory");
        asm volatile("cp.async.wait_group 2;" ::: "memory");
        __syncthreads();

        const uint32_t Ab = smb + (uint32_t)(it % NSTAGE) * STAGE_BYTES;
        const uint32_t Bb = Ab + 16384u;

        #pragma unroll
        for (int ks = 0; ks < 4; ks++) {
            uint32_t a[4][4], b[4][2];
            #pragma unroll
            for (int mi = 0; mi < 4; mi++) {
                int row = wm * 64 + mi * 16 + (q & 1) * 8 + rr;
                int kb  = ks * 32 + (q >> 1) * 16;
                LDSM4(a[mi], Ab + SWZ((uint32_t)(row * 128 + kb)));
            }
            #pragma unroll
            for (int np = 0; np < 2; np++) {
                int n  = wn * 32 + np * 16 + (q >> 1) * 8 + rr;
                int kb = ks * 32 + (q & 1) * 16;
                uint32_t t4[4];
                LDSM4(t4, Bb + SWZ((uint32_t)(n * 128 + kb)));
                b[np * 2][0] = t4[0]; b[np * 2][1] = t4[1];
                b[np * 2 + 1][0] = t4[2]; b[np * 2 + 1][1] = t4[3];
            }
            #pragma unroll
            for (int mi = 0; mi < 4; mi++)
                #pragma unroll
                for (int ni = 0; ni < 4; ni++)
                    mma16816(acc[mi][ni], a[mi], b[ni]);
        }
        __syncthreads();
    }

    // ---- epilogue: exp + target stats, all in registers --------------------
    float rowZ[4][2], rowT[4][2], colZ[4][2], colT[4][2];
    #pragma unroll
    for (int i = 0; i < 4; i++)
        #pragma unroll
        for (int j = 0; j < 2; j++) {
            rowZ[i][j] = 0.f; rowT[i][j] = 0.f; colZ[i][j] = 0.f; colT[i][j] = 0.f;
        }

    #pragma unroll
    for (int mi = 0; mi < 4; mi++) {
        const int lr0 = wm * 64 + mi * 16 + (lane >> 2);
        const int gr0 = row0 + lr0, gr1 = gr0 + 8;
        const int rl0 = rlab[lr0], rl1 = rlab[lr0 + 8];
        #pragma unroll
        for (int ni = 0; ni < 4; ni++) {
            const int lc  = wn * 32 + ni * 8 + (lane & 3) * 2;
            const int gc0 = col0 + lc, gc1 = gc0 + 1;
            const int cl0 = clab[lc], cl1 = clab[lc + 1];

            float s, e, tv;
            s = acc[mi][ni][0] * LOGIT_SCALE; e = __expf(s);
            tv = ((gr0 == gc0) || (rl0 >= 0 && rl0 == cl0)) ? s : 0.f;
            rowZ[mi][0] += e; rowT[mi][0] += tv; colZ[ni][0] += e; colT[ni][0] += tv;

            s = acc[mi][ni][1] * LOGIT_SCALE; e = __expf(s);
            tv = ((gr0 == gc1) || (rl0 >= 0 && rl0 == cl1)) ? s : 0.f;
            rowZ[mi][0] += e; rowT[mi][0] += tv; colZ[ni][1] += e; colT[ni][1] += tv;

            s = acc[mi][ni][2] * LOGIT_SCALE; e = __expf(s);
            tv = ((gr1 == gc0) || (rl1 >= 0 && rl1 == cl0)) ? s : 0.f;
            rowZ[mi][1] += e; rowT[mi][1] += tv; colZ[ni][0] += e; colT[ni][0] += tv;

            s = acc[mi][ni][3] * LOGIT_SCALE; e = __expf(s);
            tv = ((gr1 == gc1) || (rl1 >= 0 && rl1 == cl1)) ? s : 0.f;
            rowZ[mi][1] += e; rowT[mi][1] += tv; colZ[ni][1] += e; colT[ni][1] += tv;
        }
    }

    // stats smem (reuses stage buffers; last __syncthreads() already passed)
    float* rz = (float*)sm;          // [4 warp_n][128 rows]
    float* rt = rz + 512;
    float* cz = rt + 512;            // [2 warp_m][128 cols]
    float* ct = cz + 256;

    #pragma unroll
    for (int mi = 0; mi < 4; mi++)
        #pragma unroll
        for (int h = 0; h < 2; h++) {
            float z = rowZ[mi][h], t = rowT[mi][h];
            z += __shfl_xor_sync(0xffffffffu, z, 1);
            z += __shfl_xor_sync(0xffffffffu, z, 2);
            t += __shfl_xor_sync(0xffffffffu, t, 1);
            t += __shfl_xor_sync(0xffffffffu, t, 2);
            if ((lane & 3) == 0) {
                int lr = wm * 64 + mi * 16 + (lane >> 2) + h * 8;
                rz[wn * 128 + lr] = z;
                rt[wn * 128 + lr] = t;
            }
        }

    #pragma unroll
    for (int ni = 0; ni < 4; ni++)
        #pragma unroll
        for (int j = 0; j < 2; j++) {
            float z = colZ[ni][j], t = colT[ni][j];
            z += __shfl_xor_sync(0xffffffffu, z, 4);
            z += __shfl_xor_sync(0xffffffffu, z, 8);
            z += __shfl_xor_sync(0xffffffffu, z, 16);
            t += __shfl_xor_sync(0xffffffffu, t, 4);
            t += __shfl_xor_sync(0xffffffffu, t, 8);
            t += __shfl_xor_sync(0xffffffffu, t, 16);
            if (lane < 4) {
                int lc = wn * 32 + ni * 8 + lane * 2 + j;
                cz[wm * 128 + lc] = z;
                ct[wm * 128 + lc] = t;
            }
        }

    __syncthreads();
    if (tid < 128) {
        float z = 0.f, t = 0.f;
        #pragma unroll
        for (int w = 0; w < 4; w++) { z += rz[w * 128 + tid]; t += rt[w * 128 + tid]; }
        g_partZr[(size_t)bn * NROWS + row0 + tid] = z;
        g_partTr[(size_t)bn * NROWS + row0 + tid] = t;
    } else {
        int c = tid - 128;
        float z = cz[c] + cz[128 + c];
        float t = ct[c] + ct[128 + c];
        g_partZc[(size_t)bm * NROWS + col0 + c] = z;
        g_partTc[(size_t)bm * NROWS + col0 + c] = t;
    }
}

// ---------------------------------------------------------------------------
// 4) per-row final combine
// ---------------------------------------------------------------------------
__global__ void reduce_rows_kernel(const int* __restrict__ labels) {
    int i = blockIdx.x * blockDim.x + threadIdx.x;
    if (i >= NROWS) return;
    float zr = 0.f, tr = 0.f, zc = 0.f, tc = 0.f;
    #pragma unroll 8
    for (int b = 0; b < NBLK; b++) {
        zr += g_partZr[(size_t)b * NROWS + i];
        tr += g_partTr[(size_t)b * NROWS + i];
        zc += g_partZc[(size_t)b * NROWS + i];
        tc += g_partTc[(size_t)b * NROWS + i];
    }
    int l = labels[i];
    float cnt = (l < 0) ? 1.0f : (float)g_hist[l];
    g_loss[i] = (logf(zr) - tr / cnt) + (logf(zc) - tc / cnt);
}

// ---------------------------------------------------------------------------
// 5) scalar reduction
// ---------------------------------------------------------------------------
__global__ void final_sum_kernel(float* __restrict__ out) {
    __shared__ float sh[256];
    float s = 0.0f;
    for (int i = threadIdx.x; i < NROWS; i += 256) s += g_loss[i];
    sh[threadIdx.x] = s;
    __syncthreads();
    for (int o = 128; o > 0; o >>= 1) {
        if (threadIdx.x < o) sh[threadIdx.x] += sh[threadIdx.x + o];
        __syncthreads();
    }
    if (threadIdx.x == 0) out[0] = sh[0] / (2.0f * (float)NROWS);
}

// ---------------------------------------------------------------------------
extern "C" void kernel_launch(void* const* d_in, const int* in_sizes, int n_in,
                              void* d_out, int out_size) {
    const float* txt    = (const float*)d_in[0];
    const float* img    = (const float*)d_in[1];
    const int*   labels = (const int*)d_in[2];
    float* out = (float*)d_out;

    cudaFuncSetAttribute(gemm_mma_kernel,
                         cudaFuncAttributeMaxDynamicSharedMemorySize, DYNSMEM);

    normalize_split_kernel<<<dim3(NROWS, 2), 128>>>(txt, img);
    zero_hist_kernel<<<1, 128>>>();
    hist_kernel<<<NROWS / 256, 256>>>(labels);
    gemm_mma_kernel<<<dim3(NBLK, NBLK), 256, DYNSMEM>>>(labels);
    reduce_rows_kernel<<<NROWS / 256, 256>>>(labels);
    final_sum_kernel<<<1, 256>>>(out);
}

// round 9
// speedup vs baseline: 4.3661x; 1.2712x over previous
#include <cuda_runtime.h>
#include <cuda_bf16.h>
#include <math.h>
#include <stdint.h>

// ===========================================================================
// UniCL loss, N=8192, D=512 — mma.sync bf16 hi/lo-split GEMM + fused stats.
//   S = 2.659 * normalize(img) @ normalize(txt)^T   (|S| <= 2.659)
//   row_loss_i = log(sum_j exp(S_ij)) - (sum_j T_ij S_ij)/cnt_i   (cols same)
// Split: x = hi + lo (bf16 each), concat along K -> K=1024 bf16 GEMM == fp32.
// R8: __launch_bounds__(256,2) -> regs<=128, 2 CTA/SM, 16 warps for latency
// hiding (R7 ran 8 warps/SM: occ 12.5%, issue 25.5%, tensor 55%).
// ===========================================================================

#define NROWS 8192
#define DDIM  512
#define KTOT  1024
#define LOGIT_SCALE 2.659f

#define BM 128
#define BN 128
#define NITER 16            // K chunks of 64 bf16 (128 B)
#define NSTAGE 3
#define STAGE_BYTES 32768u  // A 16 KB + B 16 KB
#define DYNSMEM (NSTAGE * STAGE_BYTES)
#define NBLK 64             // 8192 / 128

// ---- device scratch --------------------------------------------------------
__device__ __nv_bfloat16 g_txt_bf[NROWS * KTOT];
__device__ __nv_bfloat16 g_img_bf[NROWS * KTOT];
__device__ float g_partZr[NBLK * NROWS];
__device__ float g_partTr[NBLK * NROWS];
__device__ float g_partZc[NBLK * NROWS];
__device__ float g_partTc[NBLK * NROWS];
__device__ int   g_hist[128];
__device__ float g_loss[NROWS];

__device__ __forceinline__ uint32_t smem_u32(const void* p) {
    uint32_t a;
    asm("{ .reg .u64 t; cvta.to.shared.u64 t, %1; cvt.u32.u64 %0, t; }"
        : "=r"(a) : "l"(p));
    return a;
}
#define SWZ(b) ((b) ^ (((b) >> 3) & 0x70))

#define LDSM4(r, a)                                                            \
    asm volatile("ldmatrix.sync.aligned.m8n8.x4.shared.b16 {%0,%1,%2,%3}, [%4];" \
                 : "=r"((r)[0]), "=r"((r)[1]), "=r"((r)[2]), "=r"((r)[3])      \
                 : "r"(a))

static __device__ __forceinline__ void mma16816(float* d, const uint32_t* a,
                                                const uint32_t* b) {
    asm volatile(
        "mma.sync.aligned.m16n8k16.row.col.f32.bf16.bf16.f32 "
        "{%0,%1,%2,%3}, {%4,%5,%6,%7}, {%8,%9}, {%0,%1,%2,%3};"
        : "+f"(d[0]), "+f"(d[1]), "+f"(d[2]), "+f"(d[3])
        : "r"(a[0]), "r"(a[1]), "r"(a[2]), "r"(a[3]), "r"(b[0]), "r"(b[1]));
}

// ---------------------------------------------------------------------------
// 1) normalize + bf16 hi/lo split. grid (8192, 2), 128 threads.
// ---------------------------------------------------------------------------
__global__ void normalize_split_kernel(const float* __restrict__ txt,
                                       const float* __restrict__ img) {
    const float* src = blockIdx.y ? img : txt;
    __nv_bfloat16* dst = blockIdx.y ? g_img_bf : g_txt_bf;
    const int row = blockIdx.x, tid = threadIdx.x;

    float4 v = *(const float4*)(src + (size_t)row * DDIM + tid * 4);
    float ss = v.x * v.x + v.y * v.y + v.z * v.z + v.w * v.w;
    #pragma unroll
    for (int o = 16; o >= 1; o >>= 1) ss += __shfl_xor_sync(0xffffffffu, ss, o);
    __shared__ float sh[4];
    if ((tid & 31) == 0) sh[tid >> 5] = ss;
    __syncthreads();
    ss = sh[0] + sh[1] + sh[2] + sh[3];
    float inv = 1.0f / fmaxf(sqrtf(ss), 1e-12f);

    float x[4] = { v.x * inv, v.y * inv, v.z * inv, v.w * inv };
    __nv_bfloat16 h[4], l[4];
    #pragma unroll
    for (int i = 0; i < 4; i++) {
        h[i] = __float2bfloat16(x[i]);
        l[i] = __float2bfloat16(x[i] - __bfloat162float(h[i]));
    }
    __nv_bfloat162* ph = (__nv_bfloat162*)(dst + (size_t)row * KTOT + tid * 4);
    __nv_bfloat162* pl = (__nv_bfloat162*)(dst + (size_t)row * KTOT + 512 + tid * 4);
    __nv_bfloat162 t;
    t.x = h[0]; t.y = h[1]; ph[0] = t;
    t.x = h[2]; t.y = h[3]; ph[1] = t;
    t.x = l[0]; t.y = l[1]; pl[0] = t;
    t.x = l[2]; t.y = l[3]; pl[1] = t;
}

// ---------------------------------------------------------------------------
// 2) label histogram
// ---------------------------------------------------------------------------
__global__ void zero_hist_kernel() { if (threadIdx.x < 128) g_hist[threadIdx.x] = 0; }

__global__ void hist_kernel(const int* __restrict__ labels) {
    int i = blockIdx.x * blockDim.x + threadIdx.x;
    if (i < NROWS) {
        int l = labels[i];
        if (l >= 0 && l < 128) atomicAdd(&g_hist[l], 1);
    }
}

// ---------------------------------------------------------------------------
// 3) mma.sync GEMM + fused stats. grid (64, 64), 256 threads, 2 CTA/SM.
//    Warp grid 2x4: warp tile 64x32. 3-stage cp.async pipeline.
// ---------------------------------------------------------------------------
__global__ __launch_bounds__(256, 2)
void gemm_mma_kernel(const int* __restrict__ labels) {
    extern __shared__ char sm[];
    const uint32_t smb = smem_u32(sm);
    __shared__ int rlab[128], clab[128];

    const int tid  = threadIdx.x;
    const int wid  = tid >> 5;
    const int lane = tid & 31;
    const int bn = blockIdx.x, bm = blockIdx.y;
    const int row0 = bm * BM, col0 = bn * BN;
    const int wm = wid >> 2;     // 0..1  (64 rows each)
    const int wn = wid & 3;      // 0..3  (32 cols each)

    if (tid < 128) rlab[tid] = labels[row0 + tid];
    else           clab[tid - 128] = labels[col0 + (tid - 128)];

    const char* Ag = (const char*)g_img_bf + (size_t)row0 * (KTOT * 2);
    const char* Bg = (const char*)g_txt_bf + (size_t)col0 * (KTOT * 2);

    // issue one 128B-deep k-chunk for A and B into stage buffer
    auto issue = [&](int st) {
        uint32_t sb = smb + (uint32_t)(st % NSTAGE) * STAGE_BYTES;
        #pragma unroll
        for (int t = 0; t < 8; t++) {
            int idx = t * 256 + tid;           // 0..2047
            int isB = idx >> 10;
            int r   = (idx >> 3) & 127;
            int c   = idx & 7;
            const char* g = (isB ? Bg : Ag) + (size_t)r * (KTOT * 2) + st * 128 + c * 16;
            uint32_t d = sb + (isB ? 16384u : 0u) + SWZ((uint32_t)(r * 128 + c * 16));
            asm volatile("cp.async.cg.shared.global [%0], [%1], 16;"
                         :: "r"(d), "l"(g) : "memory");
        }
    };

    issue(0); asm volatile("cp.async.commit_group;" ::: "memory");
    issue(1); asm volatile("cp.async.commit_group;" ::: "memory");

    float acc[4][4][4];
    #pragma unroll
    for (int mi = 0; mi < 4; mi++)
        #pragma unroll
        for (int ni = 0; ni < 4; ni++)
            #pragma unroll
            for (int e = 0; e < 4; e++) acc[mi][ni][e] = 0.0f;

    const int rr = lane & 7;
    const int q  = lane >> 3;

    #pragma unroll 1
    for (int it = 0; it < NITER; it++) {
        if (it + 2 < NITER) issue(it + 2);
        asm volatile("cp.async.commit_group;" ::: "memory");
        asm volatile("cp.async.wait_group 2;" ::: "memory");
        __syncthreads();

        const uint32_t Ab = smb + (uint32_t)(it % NSTAGE) * STAGE_BYTES;
        const uint32_t Bb = Ab + 16384u;

        #pragma unroll
        for (int ks = 0; ks < 4; ks++) {
            uint32_t a[4][4], b[4][2];
            #pragma unroll
            for (int mi = 0; mi < 4; mi++) {
                int row = wm * 64 + mi * 16 + (q & 1) * 8 + rr;
                int kb  = ks * 32 + (q >> 1) * 16;
                LDSM4(a[mi], Ab + SWZ((uint32_t)(row * 128 + kb)));
            }
            #pragma unroll
            for (int np = 0; np < 2; np++) {
                int n  = wn * 32 + np * 16 + (q >> 1) * 8 + rr;
                int kb = ks * 32 + (q & 1) * 16;
                uint32_t t4[4];
                LDSM4(t4, Bb + SWZ((uint32_t)(n * 128 + kb)));
                b[np * 2][0] = t4[0]; b[np * 2][1] = t4[1];
                b[np * 2 + 1][0] = t4[2]; b[np * 2 + 1][1] = t4[3];
            }
            #pragma unroll
            for (int mi = 0; mi < 4; mi++)
                #pragma unroll
                for (int ni = 0; ni < 4; ni++)
                    mma16816(acc[mi][ni], a[mi], b[ni]);
        }
        __syncthreads();
    }

    // ---- epilogue: exp + target stats, all in registers --------------------
    float rowZ[4][2], rowT[4][2], colZ[4][2], colT[4][2];
    #pragma unroll
    for (int i = 0; i < 4; i++)
        #pragma unroll
        for (int j = 0; j < 2; j++) {
            rowZ[i][j] = 0.f; rowT[i][j] = 0.f; colZ[i][j] = 0.f; colT[i][j] = 0.f;
        }

    #pragma unroll
    for (int mi = 0; mi < 4; mi++) {
        const int lr0 = wm * 64 + mi * 16 + (lane >> 2);
        const int gr0 = row0 + lr0, gr1 = gr0 + 8;
        const int rl0 = rlab[lr0], rl1 = rlab[lr0 + 8];
        #pragma unroll
        for (int ni = 0; ni < 4; ni++) {
            const int lc  = wn * 32 + ni * 8 + (lane & 3) * 2;
            const int gc0 = col0 + lc, gc1 = gc0 + 1;
            const int cl0 = clab[lc], cl1 = clab[lc + 1];

            float s, e, tv;
            s = acc[mi][ni][0] * LOGIT_SCALE; e = __expf(s);
            tv = ((gr0 == gc0) || (rl0 >= 0 && rl0 == cl0)) ? s : 0.f;
            rowZ[mi][0] += e; rowT[mi][0] += tv; colZ[ni][0] += e; colT[ni][0] += tv;

            s = acc[mi][ni][1] * LOGIT_SCALE; e = __expf(s);
            tv = ((gr0 == gc1) || (rl0 >= 0 && rl0 == cl1)) ? s : 0.f;
            rowZ[mi][0] += e; rowT[mi][0] += tv; colZ[ni][1] += e; colT[ni][1] += tv;

            s = acc[mi][ni][2] * LOGIT_SCALE; e = __expf(s);
            tv = ((gr1 == gc0) || (rl1 >= 0 && rl1 == cl0)) ? s : 0.f;
            rowZ[mi][1] += e; rowT[mi][1] += tv; colZ[ni][0] += e; colT[ni][0] += tv;

            s = acc[mi][ni][3] * LOGIT_SCALE; e = __expf(s);
            tv = ((gr1 == gc1) || (rl1 >= 0 && rl1 == cl1)) ? s : 0.f;
            rowZ[mi][1] += e; rowT[mi][1] += tv; colZ[ni][1] += e; colT[ni][1] += tv;
        }
    }

    // stats smem (reuses stage buffers; last __syncthreads() already passed)
    float* rz = (float*)sm;          // [4 warp_n][128 rows]
    float* rt = rz + 512;
    float* cz = rt + 512;            // [2 warp_m][128 cols]
    float* ct = cz + 256;

    #pragma unroll
    for (int mi = 0; mi < 4; mi++)
        #pragma unroll
        for (int h = 0; h < 2; h++) {
            float z = rowZ[mi][h], t = rowT[mi][h];
            z += __shfl_xor_sync(0xffffffffu, z, 1);
            z += __shfl_xor_sync(0xffffffffu, z, 2);
            t += __shfl_xor_sync(0xffffffffu, t, 1);
            t += __shfl_xor_sync(0xffffffffu, t, 2);
            if ((lane & 3) == 0) {
                int lr = wm * 64 + mi * 16 + (lane >> 2) + h * 8;
                rz[wn * 128 + lr] = z;
                rt[wn * 128 + lr] = t;
            }
        }

    #pragma unroll
    for (int ni = 0; ni < 4; ni++)
        #pragma unroll
        for (int j = 0; j < 2; j++) {
            float z = colZ[ni][j], t = colT[ni][j];
            z += __shfl_xor_sync(0xffffffffu, z, 4);
            z += __shfl_xor_sync(0xffffffffu, z, 8);
            z += __shfl_xor_sync(0xffffffffu, z, 16);
            t += __shfl_xor_sync(0xffffffffu, t, 4);
            t += __shfl_xor_sync(0xffffffffu, t, 8);
            t += __shfl_xor_sync(0xffffffffu, t, 16);
            if (lane < 4) {
                int lc = wn * 32 + ni * 8 + lane * 2 + j;
                cz[wm * 128 + lc] = z;
                ct[wm * 128 + lc] = t;
            }
        }

    __syncthreads();
    if (tid < 128) {
        float z = 0.f, t = 0.f;
        #pragma unroll
        for (int w = 0; w < 4; w++) { z += rz[w * 128 + tid]; t += rt[w * 128 + tid]; }
        g_partZr[(size_t)bn * NROWS + row0 + tid] = z;
        g_partTr[(size_t)bn * NROWS + row0 + tid] = t;
    } else {
        int c = tid - 128;
        float z = cz[c] + cz[128 + c];
        float t = ct[c] + ct[128 + c];
        g_partZc[(size_t)bm * NROWS + col0 + c] = z;
        g_partTc[(size_t)bm * NROWS + col0 + c] = t;
    }
}

// ---------------------------------------------------------------------------
// 4) per-row final combine
// ---------------------------------------------------------------------------
__global__ void reduce_rows_kernel(const int* __restrict__ labels) {
    int i = blockIdx.x * blockDim.x + threadIdx.x;
    if (i >= NROWS) return;
    float zr = 0.f, tr = 0.f, zc = 0.f, tc = 0.f;
    #pragma unroll 8
    for (int b = 0; b < NBLK; b++) {
        zr += g_partZr[(size_t)b * NROWS + i];
        tr += g_partTr[(size_t)b * NROWS + i];
        zc += g_partZc[(size_t)b * NROWS + i];
        tc += g_partTc[(size_t)b * NROWS + i];
    }
    int l = labels[i];
    float cnt = (l < 0) ? 1.0f : (float)g_hist[l];
    g_loss[i] = (logf(zr) - tr / cnt) + (logf(zc) - tc / cnt);
}

// ---------------------------------------------------------------------------
// 5) scalar reduction
// ---------------------------------------------------------------------------
__global__ void final_sum_kernel(float* __restrict__ out) {
    __shared__ float sh[256];
    float s = 0.0f;
    for (int i = threadIdx.x; i < NROWS; i += 256) s += g_loss[i];
    sh[threadIdx.x] = s;
    __syncthreads();
    for (int o = 128; o > 0; o >>= 1) {
        if (threadIdx.x < o) sh[threadIdx.x] += sh[threadIdx.x + o];
        __syncthreads();
    }
    if (threadIdx.x == 0) out[0] = sh[0] / (2.0f * (float)NROWS);
}

// ---------------------------------------------------------------------------
extern "C" void kernel_launch(void* const* d_in, const int* in_sizes, int n_in,
                              void* d_out, int out_size) {
    const float* txt    = (const float*)d_in[0];
    const float* img    = (const float*)d_in[1];
    const int*   labels = (const int*)d_in[2];
    float* out = (float*)d_out;

    cudaFuncSetAttribute(gemm_mma_kernel,
                         cudaFuncAttributeMaxDynamicSharedMemorySize, DYNSMEM);

    normalize_split_kernel<<<dim3(NROWS, 2), 128>>>(txt, img);
    zero_hist_kernel<<<1, 128>>>();
    hist_kernel<<<NROWS / 256, 256>>>(labels);
    gemm_mma_kernel<<<dim3(NBLK, NBLK), 256, DYNSMEM>>>(labels);
    reduce_rows_kernel<<<NROWS / 256, 256>>>(labels);
    final_sum_kernel<<<1, 256>>>(out);
}

// round 10
// speedup vs baseline: 7.2774x; 1.6668x over previous
#include <cuda_runtime.h>
#include <cuda_bf16.h>
#include <math.h>
#include <stdint.h>

// ===========================================================================
// UniCL loss, N=8192, D=512 — mma.sync bf16 GEMM + fused softCE stats.
//   S = normalize(img) @ (2.659 * normalize(txt))^T   (|S| <= 2.659)
//   row_loss_i = log(sum_j exp(S_ij)) - (sum_j T_ij S_ij)/cnt_i   (cols same)
// R9: plain bf16 (no hi/lo split) — rel_err budget 1e-3, bf16 gives ~1e-5.
//     K halves to 512 (NITER 8). Single barrier/iter (issue AFTER barrier).
// ===========================================================================

#define NROWS 8192
#define DDIM  512
#define KTOT  512
#define LOGIT_SCALE 2.659f

#define BM 128
#define BN 128
#define NITER 8             // K chunks of 64 bf16 (128 B)
#define NSTAGE 3
#define STAGE_BYTES 32768u  // A 16 KB + B 16 KB
#define DYNSMEM (NSTAGE * STAGE_BYTES)
#define NBLK 64             // 8192 / 128

// ---- device scratch --------------------------------------------------------
__device__ __nv_bfloat16 g_txt_bf[NROWS * KTOT];   // pre-scaled by LOGIT_SCALE
__device__ __nv_bfloat16 g_img_bf[NROWS * KTOT];
__device__ float g_partZr[NBLK * NROWS];
__device__ float g_partTr[NBLK * NROWS];
__device__ float g_partZc[NBLK * NROWS];
__device__ float g_partTc[NBLK * NROWS];
__device__ int   g_hist[128];
__device__ float g_loss[NROWS];

__device__ __forceinline__ uint32_t smem_u32(const void* p) {
    uint32_t a;
    asm("{ .reg .u64 t; cvta.to.shared.u64 t, %1; cvt.u32.u64 %0, t; }"
        : "=r"(a) : "l"(p));
    return a;
}
#define SWZ(b) ((b) ^ (((b) >> 3) & 0x70))

#define LDSM4(r, a)                                                            \
    asm volatile("ldmatrix.sync.aligned.m8n8.x4.shared.b16 {%0,%1,%2,%3}, [%4];" \
                 : "=r"((r)[0]), "=r"((r)[1]), "=r"((r)[2]), "=r"((r)[3])      \
                 : "r"(a))

static __device__ __forceinline__ void mma16816(float* d, const uint32_t* a,
                                                const uint32_t* b) {
    asm volatile(
        "mma.sync.aligned.m16n8k16.row.col.f32.bf16.bf16.f32 "
        "{%0,%1,%2,%3}, {%4,%5,%6,%7}, {%8,%9}, {%0,%1,%2,%3};"
        : "+f"(d[0]), "+f"(d[1]), "+f"(d[2]), "+f"(d[3])
        : "r"(a[0]), "r"(a[1]), "r"(a[2]), "r"(a[3]), "r"(b[0]), "r"(b[1]));
}

// ---------------------------------------------------------------------------
// 1) normalize -> bf16 (text side pre-scaled by LOGIT_SCALE).
//    grid (8192, 2), 128 threads.
// ---------------------------------------------------------------------------
__global__ void normalize_bf16_kernel(const float* __restrict__ txt,
                                      const float* __restrict__ img) {
    const float* src = blockIdx.y ? img : txt;
    __nv_bfloat16* dst = blockIdx.y ? g_img_bf : g_txt_bf;
    const float post = blockIdx.y ? 1.0f : LOGIT_SCALE;
    const int row = blockIdx.x, tid = threadIdx.x;

    float4 v = *(const float4*)(src + (size_t)row * DDIM + tid * 4);
    float ss = v.x * v.x + v.y * v.y + v.z * v.z + v.w * v.w;
    #pragma unroll
    for (int o = 16; o >= 1; o >>= 1) ss += __shfl_xor_sync(0xffffffffu, ss, o);
    __shared__ float sh[4];
    if ((tid & 31) == 0) sh[tid >> 5] = ss;
    __syncthreads();
    ss = sh[0] + sh[1] + sh[2] + sh[3];
    float inv = post / fmaxf(sqrtf(ss), 1e-12f);

    __nv_bfloat162 t0, t1;
    t0.x = __float2bfloat16(v.x * inv); t0.y = __float2bfloat16(v.y * inv);
    t1.x = __float2bfloat16(v.z * inv); t1.y = __float2bfloat16(v.w * inv);
    __nv_bfloat162* p = (__nv_bfloat162*)(dst + (size_t)row * KTOT + tid * 4);
    p[0] = t0; p[1] = t1;
}

// ---------------------------------------------------------------------------
// 2) label histogram
// ---------------------------------------------------------------------------
__global__ void zero_hist_kernel() { if (threadIdx.x < 128) g_hist[threadIdx.x] = 0; }

__global__ void hist_kernel(const int* __restrict__ labels) {
    int i = blockIdx.x * blockDim.x + threadIdx.x;
    if (i < NROWS) {
        int l = labels[i];
        if (l >= 0 && l < 128) atomicAdd(&g_hist[l], 1);
    }
}

// ---------------------------------------------------------------------------
// 3) mma.sync GEMM + fused stats. grid (64, 64), 256 threads, 2 CTA/SM.
//    Warp grid 2x4 (warp tile 64x32). 3-stage cp.async, ONE barrier/iter.
// ---------------------------------------------------------------------------
__global__ __launch_bounds__(256, 2)
void gemm_mma_kernel(const int* __restrict__ labels) {
    extern __shared__ char sm[];
    const uint32_t smb = smem_u32(sm);
    __shared__ int rlab[128], clab[128];

    const int tid  = threadIdx.x;
    const int wid  = tid >> 5;
    const int lane = tid & 31;
    const int bn = blockIdx.x, bm = blockIdx.y;
    const int row0 = bm * BM, col0 = bn * BN;
    const int wm = wid >> 2;     // 0..1  (64 rows each)
    const int wn = wid & 3;      // 0..3  (32 cols each)

    if (tid < 128) rlab[tid] = labels[row0 + tid];
    else           clab[tid - 128] = labels[col0 + (tid - 128)];

    const char* Ag = (const char*)g_img_bf + (size_t)row0 * (KTOT * 2);
    const char* Bg = (const char*)g_txt_bf + (size_t)col0 * (KTOT * 2);

    // issue one 128B-deep k-chunk for A and B into stage buffer
    auto issue = [&](int st) {
        uint32_t sb = smb + (uint32_t)(st % NSTAGE) * STAGE_BYTES;
        #pragma unroll
        for (int t = 0; t < 8; t++) {
            int idx = t * 256 + tid;           // 0..2047
            int isB = idx >> 10;
            int r   = (idx >> 3) & 127;
            int c   = idx & 7;
            const char* g = (isB ? Bg : Ag) + (size_t)r * (KTOT * 2) + st * 128 + c * 16;
            uint32_t d = sb + (isB ? 16384u : 0u) + SWZ((uint32_t)(r * 128 + c * 16));
            asm volatile("cp.async.cg.shared.global [%0], [%1], 16;"
                         :: "r"(d), "l"(g) : "memory");
        }
    };

    issue(0); asm volatile("cp.async.commit_group;" ::: "memory");
    issue(1); asm volatile("cp.async.commit_group;" ::: "memory");

    float acc[4][4][4];
    #pragma unroll
    for (int mi = 0; mi < 4; mi++)
        #pragma unroll
        for (int ni = 0; ni < 4; ni++)
            #pragma unroll
            for (int e = 0; e < 4; e++) acc[mi][ni][e] = 0.0f;

    const int rr = lane & 7;
    const int q  = lane >> 3;

    // Pipeline invariant at iter `it` (uniform commits, incl. empty tail ones):
    // commits before wait = 2+it; wait_group 1 -> stages <= it complete;
    // barrier -> all warps past compute(it-1); issue(it+2) then safely
    // overwrites stage (it-1)%3.
    #pragma unroll 1
    for (int it = 0; it < NITER; it++) {
        asm volatile("cp.async.wait_group 1;" ::: "memory");
        __syncthreads();
        if (it + 2 < NITER) issue(it + 2);
        asm volatile("cp.async.commit_group;" ::: "memory");

        const uint32_t Ab = smb + (uint32_t)(it % NSTAGE) * STAGE_BYTES;
        const uint32_t Bb = Ab + 16384u;

        #pragma unroll
        for (int ks = 0; ks < 4; ks++) {
            uint32_t a[4][4], b[4][2];
            #pragma unroll
            for (int mi = 0; mi < 4; mi++) {
                int row = wm * 64 + mi * 16 + (q & 1) * 8 + rr;
                int kb  = ks * 32 + (q >> 1) * 16;
                LDSM4(a[mi], Ab + SWZ((uint32_t)(row * 128 + kb)));
            }
            #pragma unroll
            for (int np = 0; np < 2; np++) {
                int n  = wn * 32 + np * 16 + (q >> 1) * 8 + rr;
                int kb = ks * 32 + (q & 1) * 16;
                uint32_t t4[4];
                LDSM4(t4, Bb + SWZ((uint32_t)(n * 128 + kb)));
                b[np * 2][0] = t4[0]; b[np * 2][1] = t4[1];
                b[np * 2 + 1][0] = t4[2]; b[np * 2 + 1][1] = t4[3];
            }
            #pragma unroll
            for (int mi = 0; mi < 4; mi++)
                #pragma unroll
                for (int ni = 0; ni < 4; ni++)
                    mma16816(acc[mi][ni], a[mi], b[ni]);
        }
    }

    // ---- epilogue: exp + target stats, all in registers --------------------
    // Stats smem reuses stage 0; last compute (it=7) read stage 1, and the
    // iter-7 barrier guaranteed every warp is past compute(6) (stage 0).
    float rowZ[4][2], rowT[4][2], colZ[4][2], colT[4][2];
    #pragma unroll
    for (int i = 0; i < 4; i++)
        #pragma unroll
        for (int j = 0; j < 2; j++) {
            rowZ[i][j] = 0.f; rowT[i][j] = 0.f; colZ[i][j] = 0.f; colT[i][j] = 0.f;
        }

    #pragma unroll
    for (int mi = 0; mi < 4; mi++) {
        const int lr0 = wm * 64 + mi * 16 + (lane >> 2);
        const int gr0 = row0 + lr0, gr1 = gr0 + 8;
        const int rl0 = rlab[lr0], rl1 = rlab[lr0 + 8];
        #pragma unroll
        for (int ni = 0; ni < 4; ni++) {
            const int lc  = wn * 32 + ni * 8 + (lane & 3) * 2;
            const int gc0 = col0 + lc, gc1 = gc0 + 1;
            const int cl0 = clab[lc], cl1 = clab[lc + 1];

            float s, e, tv;
            s = acc[mi][ni][0]; e = __expf(s);
            tv = ((gr0 == gc0) || (rl0 >= 0 && rl0 == cl0)) ? s : 0.f;
            rowZ[mi][0] += e; rowT[mi][0] += tv; colZ[ni][0] += e; colT[ni][0] += tv;

            s = acc[mi][ni][1]; e = __expf(s);
            tv = ((gr0 == gc1) || (rl0 >= 0 && rl0 == cl1)) ? s : 0.f;
            rowZ[mi][0] += e; rowT[mi][0] += tv; colZ[ni][1] += e; colT[ni][1] += tv;

            s = acc[mi][ni][2]; e = __expf(s);
            tv = ((gr1 == gc0) || (rl1 >= 0 && rl1 == cl0)) ? s : 0.f;
            rowZ[mi][1] += e; rowT[mi][1] += tv; colZ[ni][0] += e; colT[ni][0] += tv;

            s = acc[mi][ni][3]; e = __expf(s);
            tv = ((gr1 == gc1) || (rl1 >= 0 && rl1 == cl1)) ? s : 0.f;
            rowZ[mi][1] += e; rowT[mi][1] += tv; colZ[ni][1] += e; colT[ni][1] += tv;
        }
    }

    float* rz = (float*)sm;          // [4 warp_n][128 rows]
    float* rt = rz + 512;
    float* cz = rt + 512;            // [2 warp_m][128 cols]
    float* ct = cz + 256;

    #pragma unroll
    for (int mi = 0; mi < 4; mi++)
        #pragma unroll
        for (int h = 0; h < 2; h++) {
            float z = rowZ[mi][h], t = rowT[mi][h];
            z += __shfl_xor_sync(0xffffffffu, z, 1);
            z += __shfl_xor_sync(0xffffffffu, z, 2);
            t += __shfl_xor_sync(0xffffffffu, t, 1);
            t += __shfl_xor_sync(0xffffffffu, t, 2);
            if ((lane & 3) == 0) {
                int lr = wm * 64 + mi * 16 + (lane >> 2) + h * 8;
                rz[wn * 128 + lr] = z;
                rt[wn * 128 + lr] = t;
            }
        }

    #pragma unroll
    for (int ni = 0; ni < 4; ni++)
        #pragma unroll
        for (int j = 0; j < 2; j++) {
            float z = colZ[ni][j], t = colT[ni][j];
            z += __shfl_xor_sync(0xffffffffu, z, 4);
            z += __shfl_xor_sync(0xffffffffu, z, 8);
            z += __shfl_xor_sync(0xffffffffu, z, 16);
            t += __shfl_xor_sync(0xffffffffu, t, 4);
            t += __shfl_xor_sync(0xffffffffu, t, 8);
            t += __shfl_xor_sync(0xffffffffu, t, 16);
            if (lane < 4) {
                int lc = wn * 32 + ni * 8 + lane * 2 + j;
                cz[wm * 128 + lc] = z;
                ct[wm * 128 + lc] = t;
            }
        }

    __syncthreads();
    if (tid < 128) {
        float z = 0.f, t = 0.f;
        #pragma unroll
        for (int w = 0; w < 4; w++) { z += rz[w * 128 + tid]; t += rt[w * 128 + tid]; }
        g_partZr[(size_t)bn * NROWS + row0 + tid] = z;
        g_partTr[(size_t)bn * NROWS + row0 + tid] = t;
    } else {
        int c = tid - 128;
        float z = cz[c] + cz[128 + c];
        float t = ct[c] + ct[128 + c];
        g_partZc[(size_t)bm * NROWS + col0 + c] = z;
        g_partTc[(size_t)bm * NROWS + col0 + c] = t;
    }
}

// ---------------------------------------------------------------------------
// 4) per-row final combine
// ---------------------------------------------------------------------------
__global__ void reduce_rows_kernel(const int* __restrict__ labels) {
    int i = blockIdx.x * blockDim.x + threadIdx.x;
    if (i >= NROWS) return;
    float zr = 0.f, tr = 0.f, zc = 0.f, tc = 0.f;
    #pragma unroll 8
    for (int b = 0; b < NBLK; b++) {
        zr += g_partZr[(size_t)b * NROWS + i];
        tr += g_partTr[(size_t)b * NROWS + i];
        zc += g_partZc[(size_t)b * NROWS + i];
        tc += g_partTc[(size_t)b * NROWS + i];
    }
    int l = labels[i];
    float cnt = (l < 0) ? 1.0f : (float)g_hist[l];
    g_loss[i] = (logf(zr) - tr / cnt) + (logf(zc) - tc / cnt);
}

// ---------------------------------------------------------------------------
// 5) scalar reduction
// ---------------------------------------------------------------------------
__global__ void final_sum_kernel(float* __restrict__ out) {
    __shared__ float sh[256];
    float s = 0.0f;
    for (int i = threadIdx.x; i < NROWS; i += 256) s += g_loss[i];
    sh[threadIdx.x] = s;
    __syncthreads();
    for (int o = 128; o > 0; o >>= 1) {
        if (threadIdx.x < o) sh[threadIdx.x] += sh[threadIdx.x + o];
        __syncthreads();
    }
    if (threadIdx.x == 0) out[0] = sh[0] / (2.0f * (float)NROWS);
}

// ---------------------------------------------------------------------------
extern "C" void kernel_launch(void* const* d_in, const int* in_sizes, int n_in,
                              void* d_out, int out_size) {
    const float* txt    = (const float*)d_in[0];
    const float* img    = (const float*)d_in[1];
    const int*   labels = (const int*)d_in[2];
    float* out = (float*)d_out;

    cudaFuncSetAttribute(gemm_mma_kernel,
                         cudaFuncAttributeMaxDynamicSharedMemorySize, DYNSMEM);

    normalize_bf16_kernel<<<dim3(NROWS, 2), 128>>>(txt, img);
    zero_hist_kernel<<<1, 128>>>();
    hist_kernel<<<NROWS / 256, 256>>>(labels);
    gemm_mma_kernel<<<dim3(NBLK, NBLK), 256, DYNSMEM>>>(labels);
    reduce_rows_kernel<<<NROWS / 256, 256>>>(labels);
    final_sum_kernel<<<1, 256>>>(out);
}

// round 12
// speedup vs baseline: 7.9807x; 1.0966x over previous
#include <cuda_runtime.h>
#include <cuda_bf16.h>
#include <math.h>
#include <stdint.h>

// ===========================================================================
// UniCL loss, N=8192, D=512 — mma.sync bf16 GEMM + fused softCE stats.
//   S = normalize(img) @ (2.659 * normalize(txt))^T   (|S| <= 2.659)
//   row_loss_i = log(sum_j exp(S_ij)) - (sum_j T_ij S_ij)/cnt_i   (cols same)
// R10: hoisted LDSM addresses (SWZ(row*128+kb) == row*128 + (kb ^ rr<<4)),
//      fully unrolled mainloop (compile-time stage indices), hist folded
//      into normalize. Same pipeline/epilogue as passing R9.
// ===========================================================================

#define NROWS 8192
#define DDIM  512
#define KTOT  512
#define LOGIT_SCALE 2.659f

#define BM 128
#define BN 128
#define NITER 8             // K chunks of 64 bf16 (128 B)
#define NSTAGE 3
#define STAGE_BYTES 32768u  // A 16 KB + B 16 KB
#define DYNSMEM (NSTAGE * STAGE_BYTES)
#define NBLK 64             // 8192 / 128

// ---- device scratch --------------------------------------------------------
__device__ __nv_bfloat16 g_txt_bf[NROWS * KTOT];   // pre-scaled by LOGIT_SCALE
__device__ __nv_bfloat16 g_img_bf[NROWS * KTOT];
__device__ float g_partZr[NBLK * NROWS];
__device__ float g_partTr[NBLK * NROWS];
__device__ float g_partZc[NBLK * NROWS];
__device__ float g_partTc[NBLK * NROWS];
__device__ int   g_hist[128];
__device__ float g_loss[NROWS];

__device__ __forceinline__ uint32_t smem_u32(const void* p) {
    uint32_t a;
    asm("{ .reg .u64 t; cvta.to.shared.u64 t, %1; cvt.u32.u64 %0, t; }"
        : "=r"(a) : "l"(p));
    return a;
}
#define SWZ(b) ((b) ^ (((b) >> 3) & 0x70))

#define LDSM4(r, a)                                                            \
    asm volatile("ldmatrix.sync.aligned.m8n8.x4.shared.b16 {%0,%1,%2,%3}, [%4];" \
                 : "=r"((r)[0]), "=r"((r)[1]), "=r"((r)[2]), "=r"((r)[3])      \
                 : "r"(a))

static __device__ __forceinline__ void mma16816(float* d, const uint32_t* a,
                                                const uint32_t* b) {
    asm volatile(
        "mma.sync.aligned.m16n8k16.row.col.f32.bf16.bf16.f32 "
        "{%0,%1,%2,%3}, {%4,%5,%6,%7}, {%8,%9}, {%0,%1,%2,%3};"
        : "+f"(d[0]), "+f"(d[1]), "+f"(d[2]), "+f"(d[3])
        : "r"(a[0]), "r"(a[1]), "r"(a[2]), "r"(a[3]), "r"(b[0]), "r"(b[1]));
}

// ---------------------------------------------------------------------------
// 1) normalize -> bf16 (text pre-scaled by LOGIT_SCALE); label histogram
//    folded in (one atomicAdd per row, img pass only; zero_hist runs before).
//    grid (8192, 2), 128 threads.
// ---------------------------------------------------------------------------
__global__ void normalize_bf16_kernel(const float* __restrict__ txt,
                                      const float* __restrict__ img,
                                      const int* __restrict__ labels) {
    const float* src = blockIdx.y ? img : txt;
    __nv_bfloat16* dst = blockIdx.y ? g_img_bf : g_txt_bf;
    const float post = blockIdx.y ? 1.0f : LOGIT_SCALE;
    const int row = blockIdx.x, tid = threadIdx.x;

    if (blockIdx.y && tid == 0) {
        int l = labels[row];
        if (l >= 0 && l < 128) atomicAdd(&g_hist[l], 1);
    }

    float4 v = *(const float4*)(src + (size_t)row * DDIM + tid * 4);
    float ss = v.x * v.x + v.y * v.y + v.z * v.z + v.w * v.w;
    #pragma unroll
    for (int o = 16; o >= 1; o >>= 1) ss += __shfl_xor_sync(0xffffffffu, ss, o);
    __shared__ float sh[4];
    if ((tid & 31) == 0) sh[tid >> 5] = ss;
    __syncthreads();
    ss = sh[0] + sh[1] + sh[2] + sh[3];
    float inv = post / fmaxf(sqrtf(ss), 1e-12f);

    __nv_bfloat162 t0, t1;
    t0.x = __float2bfloat16(v.x * inv); t0.y = __float2bfloat16(v.y * inv);
    t1.x = __float2bfloat16(v.z * inv); t1.y = __float2bfloat16(v.w * inv);
    __nv_bfloat162* p = (__nv_bfloat162*)(dst + (size_t)row * KTOT + tid * 4);
    p[0] = t0; p[1] = t1;
}

__global__ void zero_hist_kernel() { if (threadIdx.x < 128) g_hist[threadIdx.x] = 0; }

// ---------------------------------------------------------------------------
// 2) mma.sync GEMM + fused stats. grid (64, 64), 256 threads, 2 CTA/SM.
//    Warp grid 2x4 (warp tile 64x32). 3-stage cp.async, one barrier/iter,
//    fully unrolled mainloop, hoisted LDSM addresses.
// ---------------------------------------------------------------------------
__global__ __launch_bounds__(256, 2)
void gemm_mma_kernel(const int* __restrict__ labels) {
    extern __shared__ char sm[];
    const uint32_t smb = smem_u32(sm);
    __shared__ int rlab[128], clab[128];

    const int tid  = threadIdx.x;
    const int wid  = tid >> 5;
    const int lane = tid & 31;
    const int bn = blockIdx.x, bm = blockIdx.y;
    const int row0 = bm * BM, col0 = bn * BN;
    const int wm = wid >> 2;     // 0..1  (64 rows each)
    const int wn = wid & 3;      // 0..3  (32 cols each)

    if (tid < 128) rlab[tid] = labels[row0 + tid];
    else           clab[tid - 128] = labels[col0 + (tid - 128)];

    const char* Ag = (const char*)g_img_bf + (size_t)row0 * (KTOT * 2);
    const char* Bg = (const char*)g_txt_bf + (size_t)col0 * (KTOT * 2);

    // issue one 128B-deep k-chunk for A and B into stage buffer
    auto issue = [&](int st) {
        uint32_t sb = smb + (uint32_t)(st % NSTAGE) * STAGE_BYTES;
        #pragma unroll
        for (int t = 0; t < 8; t++) {
            int idx = t * 256 + tid;           // 0..2047
            int isB = idx >> 10;
            int r   = (idx >> 3) & 127;
            int c   = idx & 7;
            const char* g = (isB ? Bg : Ag) + (size_t)r * (KTOT * 2) + st * 128 + c * 16;
            uint32_t d = sb + (isB ? 16384u : 0u) + SWZ((uint32_t)(r * 128 + c * 16));
            asm volatile("cp.async.cg.shared.global [%0], [%1], 16;"
                         :: "r"(d), "l"(g) : "memory");
        }
    };

    issue(0); asm volatile("cp.async.commit_group;" ::: "memory");
    issue(1); asm volatile("cp.async.commit_group;" ::: "memory");

    float acc[4][4][4];
    #pragma unroll
    for (int mi = 0; mi < 4; mi++)
        #pragma unroll
        for (int ni = 0; ni < 4; ni++)
            #pragma unroll
            for (int e = 0; e < 4; e++) acc[mi][ni][e] = 0.0f;

    const int rr = lane & 7;
    const int q  = lane >> 3;

    // Hoisted LDSM address components.
    // SWZ(row*128 + kb) == row*128 + (kb ^ (rr<<4)) because row&7 == rr and
    // kb < 128, so each LDSM address is base + rowX[] + kX[].
    uint32_t rowA[4], rowB[2], kA[4], kB[4];
    #pragma unroll
    for (int mi = 0; mi < 4; mi++)
        rowA[mi] = (uint32_t)((wm * 64 + mi * 16 + (q & 1) * 8 + rr) * 128);
    #pragma unroll
    for (int np = 0; np < 2; np++)
        rowB[np] = (uint32_t)((wn * 32 + np * 16 + (q >> 1) * 8 + rr) * 128);
    #pragma unroll
    for (int ks = 0; ks < 4; ks++) {
        kA[ks] = (uint32_t)((ks * 32 + (q >> 1) * 16) ^ (rr << 4));
        kB[ks] = (uint32_t)((ks * 32 + (q & 1) * 16) ^ (rr << 4));
    }

    // Pipeline invariant at iter `it` (uniform commits, incl. empty tail ones):
    // commits before wait = 2+it; wait_group 1 -> stages <= it complete;
    // barrier -> all warps past compute(it-1); issue(it+2) then safely
    // overwrites stage (it-1)%3. Fully unrolled: stage bases are constants.
    #pragma unroll
    for (int it = 0; it < NITER; it++) {
        asm volatile("cp.async.wait_group 1;" ::: "memory");
        __syncthreads();
        if (it + 2 < NITER) issue(it + 2);
        asm volatile("cp.async.commit_group;" ::: "memory");

        const uint32_t Ab = smb + (uint32_t)(it % NSTAGE) * STAGE_BYTES;
        const uint32_t Bb = Ab + 16384u;

        #pragma unroll
        for (int ks = 0; ks < 4; ks++) {
            uint32_t a[4][4], b[4][2];
            #pragma unroll
            for (int mi = 0; mi < 4; mi++)
                LDSM4(a[mi], Ab + rowA[mi] + kA[ks]);
            #pragma unroll
            for (int np = 0; np < 2; np++) {
                uint32_t t4[4];
                LDSM4(t4, Bb + rowB[np] + kB[ks]);
                b[np * 2][0] = t4[0]; b[np * 2][1] = t4[1];
                b[np * 2 + 1][0] = t4[2]; b[np * 2 + 1][1] = t4[3];
            }
            #pragma unroll
            for (int mi = 0; mi < 4; mi++)
                #pragma unroll
                for (int ni = 0; ni < 4; ni++)
                    mma16816(acc[mi][ni], a[mi], b[ni]);
        }
    }

    // ---- epilogue: exp + target stats, all in registers --------------------
    // Stats smem (offsets 0..6143) reuses stage 0/low part; last compute
    // (it=7) reads stage 1 (32768+), and every warp passed the it=7 barrier.
    float rowZ[4][2], rowT[4][2], colZ[4][2], colT[4][2];
    #pragma unroll
    for (int i = 0; i < 4; i++)
        #pragma unroll
        for (int j = 0; j < 2; j++) {
            rowZ[i][j] = 0.f; rowT[i][j] = 0.f; colZ[i][j] = 0.f; colT[i][j] = 0.f;
        }

    #pragma unroll
    for (int mi = 0; mi < 4; mi++) {
        const int lr0 = wm * 64 + mi * 16 + (lane >> 2);
        const int gr0 = row0 + lr0, gr1 = gr0 + 8;
        const int rl0 = rlab[lr0], rl1 = rlab[lr0 + 8];
        #pragma unroll
        for (int ni = 0; ni < 4; ni++) {
            const int lc  = wn * 32 + ni * 8 + (lane & 3) * 2;
            const int gc0 = col0 + lc, gc1 = gc0 + 1;
            const int cl0 = clab[lc], cl1 = clab[lc + 1];

            float s, e, tv;
            s = acc[mi][ni][0]; e = __expf(s);
            tv = ((gr0 == gc0) || (rl0 >= 0 && rl0 == cl0)) ? s : 0.f;
            rowZ[mi][0] += e; rowT[mi][0] += tv; colZ[ni][0] += e; colT[ni][0] += tv;

            s = acc[mi][ni][1]; e = __expf(s);
            tv = ((gr0 == gc1) || (rl0 >= 0 && rl0 == cl1)) ? s : 0.f;
            rowZ[mi][0] += e; rowT[mi][0] += tv; colZ[ni][1] += e; colT[ni][1] += tv;

            s = acc[mi][ni][2]; e = __expf(s);
            tv = ((gr1 == gc0) || (rl1 >= 0 && rl1 == cl0)) ? s : 0.f;
            rowZ[mi][1] += e; rowT[mi][1] += tv; colZ[ni][0] += e; colT[ni][0] += tv;

            s = acc[mi][ni][3]; e = __expf(s);
            tv = ((gr1 == gc1) || (rl1 >= 0 && rl1 == cl1)) ? s : 0.f;
            rowZ[mi][1] += e; rowT[mi][1] += tv; colZ[ni][1] += e; colT[ni][1] += tv;
        }
    }

    float* rz = (float*)sm;          // [4 warp_n][128 rows]
    float* rt = rz + 512;
    float* cz = rt + 512;            // [2 warp_m][128 cols]
    float* ct = cz + 256;

    #pragma unroll
    for (int mi = 0; mi < 4; mi++)
        #pragma unroll
        for (int h = 0; h < 2; h++) {
            float z = rowZ[mi][h], t = rowT[mi][h];
            z += __shfl_xor_sync(0xffffffffu, z, 1);
            z += __shfl_xor_sync(0xffffffffu, z, 2);
            t += __shfl_xor_sync(0xffffffffu, t, 1);
            t += __shfl_xor_sync(0xffffffffu, t, 2);
            if ((lane & 3) == 0) {
                int lr = wm * 64 + mi * 16 + (lane >> 2) + h * 8;
                rz[wn * 128 + lr] = z;
                rt[wn * 128 + lr] = t;
            }
        }

    #pragma unroll
    for (int ni = 0; ni < 4; ni++)
        #pragma unroll
        for (int j = 0; j < 2; j++) {
            float z = colZ[ni][j], t = colT[ni][j];
            z += __shfl_xor_sync(0xffffffffu, z, 4);
            z += __shfl_xor_sync(0xffffffffu, z, 8);
            z += __shfl_xor_sync(0xffffffffu, z, 16);
            t += __shfl_xor_sync(0xffffffffu, t, 4);
            t += __shfl_xor_sync(0xffffffffu, t, 8);
            t += __shfl_xor_sync(0xffffffffu, t, 16);
            if (lane < 4) {
                int lc = wn * 32 + ni * 8 + lane * 2 + j;
                cz[wm * 128 + lc] = z;
                ct[wm * 128 + lc] = t;
            }
        }

    __syncthreads();
    if (tid < 128) {
        float z = 0.f, t = 0.f;
        #pragma unroll
        for (int w = 0; w < 4; w++) { z += rz[w * 128 + tid]; t += rt[w * 128 + tid]; }
        g_partZr[(size_t)bn * NROWS + row0 + tid] = z;
        g_partTr[(size_t)bn * NROWS + row0 + tid] = t;
    } else {
        int c = tid - 128;
        float z = cz[c] + cz[128 + c];
        float t = ct[c] + ct[128 + c];
        g_partZc[(size_t)bm * NROWS + col0 + c] = z;
        g_partTc[(size_t)bm * NROWS + col0 + c] = t;
    }
}

// ---------------------------------------------------------------------------
// 3) per-row final combine
// ---------------------------------------------------------------------------
__global__ void reduce_rows_kernel(const int* __restrict__ labels) {
    int i = blockIdx.x * blockDim.x + threadIdx.x;
    if (i >= NROWS) return;
    float zr = 0.f, tr = 0.f, zc = 0.f, tc = 0.f;
    #pragma unroll 8
    for (int b = 0; b < NBLK; b++) {
        zr += g_partZr[(size_t)b * NROWS + i];
        tr += g_partTr[(size_t)b * NROWS + i];
        zc += g_partZc[(size_t)b * NROWS + i];
        tc += g_partTc[(size_t)b * NROWS + i];
    }
    int l = labels[i];
    float cnt = (l < 0) ? 1.0f : (float)g_hist[l];
    g_loss[i] = (logf(zr) - tr / cnt) + (logf(zc) - tc / cnt);
}

// ---------------------------------------------------------------------------
// 4) scalar reduction
// ---------------------------------------------------------------------------
__global__ void final_sum_kernel(float* __restrict__ out) {
    __shared__ float sh[256];
    float s = 0.0f;
    for (int i = threadIdx.x; i < NROWS; i += 256) s += g_loss[i];
    sh[threadIdx.x] = s;
    __syncthreads();
    for (int o = 128; o > 0; o >>= 1) {
        if (threadIdx.x < o) sh[threadIdx.x] += sh[threadIdx.x + o];
        __syncthreads();
    }
    if (threadIdx.x == 0) out[0] = sh[0] / (2.0f * (float)NROWS);
}

// ---------------------------------------------------------------------------
extern "C" void kernel_launch(void* const* d_in, const int* in_sizes, int n_in,
                              void* d_out, int out_size) {
    const float* txt    = (const float*)d_in[0];
    const float* img    = (const float*)d_in[1];
    const int*   labels = (const int*)d_in[2];
    float* out = (float*)d_out;

    cudaFuncSetAttribute(gemm_mma_kernel,
                         cudaFuncAttributeMaxDynamicSharedMemorySize, DYNSMEM);

    zero_hist_kernel<<<1, 128>>>();
    normalize_bf16_kernel<<<dim3(NROWS, 2), 128>>>(txt, img, labels);
    gemm_mma_kernel<<<dim3(NBLK, NBLK), 256, DYNSMEM>>>(labels);
    reduce_rows_kernel<<<NROWS / 256, 256>>>(labels);
    final_sum_kernel<<<1, 256>>>(out);
}

// round 16
// speedup vs baseline: 8.2483x; 1.0335x over previous
#include <cuda_runtime.h>
#include <cuda_bf16.h>
#include <math.h>
#include <stdint.h>

// ===========================================================================
// UniCL loss, N=8192, D=512 — mma.sync bf16 GEMM + fused softCE stats.
//   S = normalize(img) @ (2.659 * normalize(txt))^T   (|S| <= 2.659)
//   row_loss_i = log(sum_j exp(S_ij)) - (sum_j T_ij S_ij)/cnt_i   (cols same)
// R12: reduce_rows gets 4x thread parallelism (thread = (row, array), quad
//      shfl combine); final_sum vectorized 1024-thread block. GEMM identical
//      to passing R11 (hoisted LDSM addresses, unrolled, 2 CTA/SM).
// ===========================================================================

#define NROWS 8192
#define DDIM  512
#define KTOT  512
#define LOGIT_SCALE 2.659f

#define BM 128
#define BN 128
#define NITER 8             // K chunks of 64 bf16 (128 B)
#define NSTAGE 3
#define STAGE_BYTES 32768u  // A 16 KB + B 16 KB
#define DYNSMEM (NSTAGE * STAGE_BYTES)
#define NBLK 64             // 8192 / 128

// ---- device scratch --------------------------------------------------------
__device__ __nv_bfloat16 g_txt_bf[NROWS * KTOT];   // pre-scaled by LOGIT_SCALE
__device__ __nv_bfloat16 g_img_bf[NROWS * KTOT];
__device__ float g_partZr[NBLK * NROWS];
__device__ float g_partTr[NBLK * NROWS];
__device__ float g_partZc[NBLK * NROWS];
__device__ float g_partTc[NBLK * NROWS];
__device__ int   g_hist[128];
__device__ float g_loss[NROWS];

__device__ __forceinline__ uint32_t smem_u32(const void* p) {
    uint32_t a;
    asm("{ .reg .u64 t; cvta.to.shared.u64 t, %1; cvt.u32.u64 %0, t; }"
        : "=r"(a) : "l"(p));
    return a;
}
#define SWZ(b) ((b) ^ (((b) >> 3) & 0x70))

#define LDSM4(r, a)                                                            \
    asm volatile("ldmatrix.sync.aligned.m8n8.x4.shared.b16 {%0,%1,%2,%3}, [%4];" \
                 : "=r"((r)[0]), "=r"((r)[1]), "=r"((r)[2]), "=r"((r)[3])      \
                 : "r"(a))

static __device__ __forceinline__ void mma16816(float* d, const uint32_t* a,
                                                const uint32_t* b) {
    asm volatile(
        "mma.sync.aligned.m16n8k16.row.col.f32.bf16.bf16.f32 "
        "{%0,%1,%2,%3}, {%4,%5,%6,%7}, {%8,%9}, {%0,%1,%2,%3};"
        : "+f"(d[0]), "+f"(d[1]), "+f"(d[2]), "+f"(d[3])
        : "r"(a[0]), "r"(a[1]), "r"(a[2]), "r"(a[3]), "r"(b[0]), "r"(b[1]));
}

// ---------------------------------------------------------------------------
// 1) normalize -> bf16 (text pre-scaled by LOGIT_SCALE); label histogram
//    folded in (one atomicAdd per row, img pass only; zero_hist runs before).
//    grid (8192, 2), 128 threads.
// ---------------------------------------------------------------------------
__global__ void normalize_bf16_kernel(const float* __restrict__ txt,
                                      const float* __restrict__ img,
                                      const int* __restrict__ labels) {
    const float* src = blockIdx.y ? img : txt;
    __nv_bfloat16* dst = blockIdx.y ? g_img_bf : g_txt_bf;
    const float post = blockIdx.y ? 1.0f : LOGIT_SCALE;
    const int row = blockIdx.x, tid = threadIdx.x;

    if (blockIdx.y && tid == 0) {
        int l = labels[row];
        if (l >= 0 && l < 128) atomicAdd(&g_hist[l], 1);
    }

    float4 v = *(const float4*)(src + (size_t)row * DDIM + tid * 4);
    float ss = v.x * v.x + v.y * v.y + v.z * v.z + v.w * v.w;
    #pragma unroll
    for (int o = 16; o >= 1; o >>= 1) ss += __shfl_xor_sync(0xffffffffu, ss, o);
    __shared__ float sh[4];
    if ((tid & 31) == 0) sh[tid >> 5] = ss;
    __syncthreads();
    ss = sh[0] + sh[1] + sh[2] + sh[3];
    float inv = post / fmaxf(sqrtf(ss), 1e-12f);

    __nv_bfloat162 t0, t1;
    t0.x = __float2bfloat16(v.x * inv); t0.y = __float2bfloat16(v.y * inv);
    t1.x = __float2bfloat16(v.z * inv); t1.y = __float2bfloat16(v.w * inv);
    __nv_bfloat162* p = (__nv_bfloat162*)(dst + (size_t)row * KTOT + tid * 4);
    p[0] = t0; p[1] = t1;
}

__global__ void zero_hist_kernel() { if (threadIdx.x < 128) g_hist[threadIdx.x] = 0; }

// ---------------------------------------------------------------------------
// 2) mma.sync GEMM + fused stats. grid (64, 64), 256 threads, 2 CTA/SM.
//    Warp grid 2x4 (warp tile 64x32). 3-stage cp.async, one barrier/iter,
//    fully unrolled mainloop, hoisted LDSM addresses.  (identical to R11)
// ---------------------------------------------------------------------------
__global__ __launch_bounds__(256, 2)
void gemm_mma_kernel(const int* __restrict__ labels) {
    extern __shared__ char sm[];
    const uint32_t smb = smem_u32(sm);
    __shared__ int rlab[128], clab[128];

    const int tid  = threadIdx.x;
    const int wid  = tid >> 5;
    const int lane = tid & 31;
    const int bn = blockIdx.x, bm = blockIdx.y;
    const int row0 = bm * BM, col0 = bn * BN;
    const int wm = wid >> 2;     // 0..1  (64 rows each)
    const int wn = wid & 3;      // 0..3  (32 cols each)

    if (tid < 128) rlab[tid] = labels[row0 + tid];
    else           clab[tid - 128] = labels[col0 + (tid - 128)];

    const char* Ag = (const char*)g_img_bf + (size_t)row0 * (KTOT * 2);
    const char* Bg = (const char*)g_txt_bf + (size_t)col0 * (KTOT * 2);

    // issue one 128B-deep k-chunk for A and B into stage buffer
    auto issue = [&](int st) {
        uint32_t sb = smb + (uint32_t)(st % NSTAGE) * STAGE_BYTES;
        #pragma unroll
        for (int t = 0; t < 8; t++) {
            int idx = t * 256 + tid;           // 0..2047
            int isB = idx >> 10;
            int r   = (idx >> 3) & 127;
            int c   = idx & 7;
            const char* g = (isB ? Bg : Ag) + (size_t)r * (KTOT * 2) + st * 128 + c * 16;
            uint32_t d = sb + (isB ? 16384u : 0u) + SWZ((uint32_t)(r * 128 + c * 16));
            asm volatile("cp.async.cg.shared.global [%0], [%1], 16;"
                         :: "r"(d), "l"(g) : "memory");
        }
    };

    issue(0); asm volatile("cp.async.commit_group;" ::: "memory");
    issue(1); asm volatile("cp.async.commit_group;" ::: "memory");

    float acc[4][4][4];
    #pragma unroll
    for (int mi = 0; mi < 4; mi++)
        #pragma unroll
        for (int ni = 0; ni < 4; ni++)
            #pragma unroll
            for (int e = 0; e < 4; e++) acc[mi][ni][e] = 0.0f;

    const int rr = lane & 7;
    const int q  = lane >> 3;

    // Hoisted LDSM address components.
    // SWZ(row*128 + kb) == row*128 + (kb ^ (rr<<4)) because row&7 == rr and
    // kb < 128, so each LDSM address is base + rowX[] + kX[].
    uint32_t rowA[4], rowB[2], kA[4], kB[4];
    #pragma unroll
    for (int mi = 0; mi < 4; mi++)
        rowA[mi] = (uint32_t)((wm * 64 + mi * 16 + (q & 1) * 8 + rr) * 128);
    #pragma unroll
    for (int np = 0; np < 2; np++)
        rowB[np] = (uint32_t)((wn * 32 + np * 16 + (q >> 1) * 8 + rr) * 128);
    #pragma unroll
    for (int ks = 0; ks < 4; ks++) {
        kA[ks] = (uint32_t)((ks * 32 + (q >> 1) * 16) ^ (rr << 4));
        kB[ks] = (uint32_t)((ks * 32 + (q & 1) * 16) ^ (rr << 4));
    }

    // Pipeline invariant at iter `it` (uniform commits, incl. empty tail ones):
    // commits before wait = 2+it; wait_group 1 -> stages <= it complete;
    // barrier -> all warps past compute(it-1); issue(it+2) then safely
    // overwrites stage (it-1)%3. Fully unrolled: stage bases are constants.
    #pragma unroll
    for (int it = 0; it < NITER; it++) {
        asm volatile("cp.async.wait_group 1;" ::: "memory");
        __syncthreads();
        if (it + 2 < NITER) issue(it + 2);
        asm volatile("cp.async.commit_group;" ::: "memory");

        const uint32_t Ab = smb + (uint32_t)(it % NSTAGE) * STAGE_BYTES;
        const uint32_t Bb = Ab + 16384u;

        #pragma unroll
        for (int ks = 0; ks < 4; ks++) {
            uint32_t a[4][4], b[4][2];
            #pragma unroll
            for (int mi = 0; mi < 4; mi++)
                LDSM4(a[mi], Ab + rowA[mi] + kA[ks]);
            #pragma unroll
            for (int np = 0; np < 2; np++) {
                uint32_t t4[4];
                LDSM4(t4, Bb + rowB[np] + kB[ks]);
                b[np * 2][0] = t4[0]; b[np * 2][1] = t4[1];
                b[np * 2 + 1][0] = t4[2]; b[np * 2 + 1][1] = t4[3];
            }
            #pragma unroll
            for (int mi = 0; mi < 4; mi++)
                #pragma unroll
                for (int ni = 0; ni < 4; ni++)
                    mma16816(acc[mi][ni], a[mi], b[ni]);
        }
    }

    // ---- epilogue: exp + target stats, all in registers --------------------
    float rowZ[4][2], rowT[4][2], colZ[4][2], colT[4][2];
    #pragma unroll
    for (int i = 0; i < 4; i++)
        #pragma unroll
        for (int j = 0; j < 2; j++) {
            rowZ[i][j] = 0.f; rowT[i][j] = 0.f; colZ[i][j] = 0.f; colT[i][j] = 0.f;
        }

    #pragma unroll
    for (int mi = 0; mi < 4; mi++) {
        const int lr0 = wm * 64 + mi * 16 + (lane >> 2);
        const int gr0 = row0 + lr0, gr1 = gr0 + 8;
        const int rl0 = rlab[lr0], rl1 = rlab[lr0 + 8];
        #pragma unroll
        for (int ni = 0; ni < 4; ni++) {
            const int lc  = wn * 32 + ni * 8 + (lane & 3) * 2;
            const int gc0 = col0 + lc, gc1 = gc0 + 1;
            const int cl0 = clab[lc], cl1 = clab[lc + 1];

            float s, e, tv;
            s = acc[mi][ni][0]; e = __expf(s);
            tv = ((gr0 == gc0) || (rl0 >= 0 && rl0 == cl0)) ? s : 0.f;
            rowZ[mi][0] += e; rowT[mi][0] += tv; colZ[ni][0] += e; colT[ni][0] += tv;

            s = acc[mi][ni][1]; e = __expf(s);
            tv = ((gr0 == gc1) || (rl0 >= 0 && rl0 == cl1)) ? s : 0.f;
            rowZ[mi][0] += e; rowT[mi][0] += tv; colZ[ni][1] += e; colT[ni][1] += tv;

            s = acc[mi][ni][2]; e = __expf(s);
            tv = ((gr1 == gc0) || (rl1 >= 0 && rl1 == cl0)) ? s : 0.f;
            rowZ[mi][1] += e; rowT[mi][1] += tv; colZ[ni][0] += e; colT[ni][0] += tv;

            s = acc[mi][ni][3]; e = __expf(s);
            tv = ((gr1 == gc1) || (rl1 >= 0 && rl1 == cl1)) ? s : 0.f;
            rowZ[mi][1] += e; rowT[mi][1] += tv; colZ[ni][1] += e; colT[ni][1] += tv;
        }
    }

    float* rz = (float*)sm;          // [4 warp_n][128 rows]
    float* rt = rz + 512;
    float* cz = rt + 512;            // [2 warp_m][128 cols]
    float* ct = cz + 256;

    #pragma unroll
    for (int mi = 0; mi < 4; mi++)
        #pragma unroll
        for (int h = 0; h < 2; h++) {
            float z = rowZ[mi][h], t = rowT[mi][h];
            z += __shfl_xor_sync(0xffffffffu, z, 1);
            z += __shfl_xor_sync(0xffffffffu, z, 2);
            t += __shfl_xor_sync(0xffffffffu, t, 1);
            t += __shfl_xor_sync(0xffffffffu, t, 2);
            if ((lane & 3) == 0) {
                int lr = wm * 64 + mi * 16 + (lane >> 2) + h * 8;
                rz[wn * 128 + lr] = z;
                rt[wn * 128 + lr] = t;
            }
        }

    #pragma unroll
    for (int ni = 0; ni < 4; ni++)
        #pragma unroll
        for (int j = 0; j < 2; j++) {
            float z = colZ[ni][j], t = colT[ni][j];
            z += __shfl_xor_sync(0xffffffffu, z, 4);
            z += __shfl_xor_sync(0xffffffffu, z, 8);
            z += __shfl_xor_sync(0xffffffffu, z, 16);
            t += __shfl_xor_sync(0xffffffffu, t, 4);
            t += __shfl_xor_sync(0xffffffffu, t, 8);
            t += __shfl_xor_sync(0xffffffffu, t, 16);
            if (lane < 4) {
                int lc = wn * 32 + ni * 8 + lane * 2 + j;
                cz[wm * 128 + lc] = z;
                ct[wm * 128 + lc] = t;
            }
        }

    __syncthreads();
    if (tid < 128) {
        float z = 0.f, t = 0.f;
        #pragma unroll
        for (int w = 0; w < 4; w++) { z += rz[w * 128 + tid]; t += rt[w * 128 + tid]; }
        g_partZr[(size_t)bn * NROWS + row0 + tid] = z;
        g_partTr[(size_t)bn * NROWS + row0 + tid] = t;
    } else {
        int c = tid - 128;
        float z = cz[c] + cz[128 + c];
        float t = ct[c] + ct[128 + c];
        g_partZc[(size_t)bm * NROWS + col0 + c] = z;
        g_partTc[(size_t)bm * NROWS + col0 + c] = t;
    }
}

// ---------------------------------------------------------------------------
// 3) per-row final combine. One thread per (row, array): 32768 threads /
//    128 CTAs. Same ascending-b sum order as before (bit-identical), quad
//    shfl gathers the 4 sums, lane which==0 writes the loss.
// ---------------------------------------------------------------------------
__global__ void reduce_rows_kernel(const int* __restrict__ labels) {
    const int gid   = blockIdx.x * blockDim.x + threadIdx.x;  // 0..32767
    const int i     = gid >> 2;
    const int which = gid & 3;
    const float* __restrict__ src =
        (which == 0) ? g_partZr : (which == 1) ? g_partTr
      : (which == 2) ? g_partZc : g_partTc;

    float s = 0.f;
    #pragma unroll 8
    for (int b = 0; b < NBLK; b++) s += src[(size_t)b * NROWS + i];

    const unsigned m = 0xffffffffu;
    const int base = threadIdx.x & ~3;
    float zr = __shfl_sync(m, s, base + 0);
    float tr = __shfl_sync(m, s, base + 1);
    float zc = __shfl_sync(m, s, base + 2);
    float tc = __shfl_sync(m, s, base + 3);

    if (which == 0) {
        int l = labels[i];
        float cnt = (l < 0) ? 1.0f : (float)g_hist[l];
        g_loss[i] = (logf(zr) - tr / cnt) + (logf(zc) - tc / cnt);
    }
}

// ---------------------------------------------------------------------------
// 4) scalar reduction: 1024 threads, float4 loads (2 per thread).
// ---------------------------------------------------------------------------
__global__ void final_sum_kernel(float* __restrict__ out) {
    __shared__ float sh[1024];
    const int t = threadIdx.x;
    const float4* p = (const float4*)g_loss;       // 2048 float4
    float4 v = p[t];
    float4 w = p[t + 1024];
    sh[t] = (v.x + v.y + v.z + v.w) + (w.x + w.y + w.z + w.w);
    __syncthreads();
    #pragma unroll
    for (int o = 512; o > 0; o >>= 1) {
        if (t < o) sh[t] += sh[t + o];
        __syncthreads();
    }
    if (t == 0) out[0] = sh[0] / (2.0f * (float)NROWS);
}

// ---------------------------------------------------------------------------
extern "C" void kernel_launch(void* const* d_in, const int* in_sizes, int n_in,
                              void* d_out, int out_size) {
    const float* txt    = (const float*)d_in[0];
    const float* img    = (const float*)d_in[1];
    const int*   labels = (const int*)d_in[2];
    float* out = (float*)d_out;

    cudaFuncSetAttribute(gemm_mma_kernel,
                         cudaFuncAttributeMaxDynamicSharedMemorySize, DYNSMEM);

    zero_hist_kernel<<<1, 128>>>();
    normalize_bf16_kernel<<<dim3(NROWS, 2), 128>>>(txt, img, labels);
    gemm_mma_kernel<<<dim3(NBLK, NBLK), 256, DYNSMEM>>>(labels);
    reduce_rows_kernel<<<(NROWS * 4) / 256, 256>>>(labels);
    final_sum_kernel<<<1, 1024>>>(out);
}